// round 1
// baseline (speedup 1.0000x reference)
#include <cuda_runtime.h>
#include <cuda_bf16.h>

// Problem constants
#define T_SEQ 4096
#define C_DIM 768
#define NHEAD 12
#define DHEAD 64
#define QKV_N (3 * C_DIM)   // 2304

// Scratch (allocation-free rule: device globals)
__device__ float g_qkv[T_SEQ * QKV_N];   // [T, 3C]
__device__ float g_y[T_SEQ * C_DIM];     // [T, C] attention output (head-interleaved = natural)

// ---------------------------------------------------------------------------
// Classic SGEMM: C[M,N] = A[M,K] @ B[K,N] + bias[N]
// BM=BN=128, BK=8, 256 threads, 8x8 register tile per thread.
// Requires M%128==0, N%128==0, K%8==0 (true for all our calls).
// ---------------------------------------------------------------------------
__global__ void __launch_bounds__(256) sgemm_bias_kernel(
    const float* __restrict__ A, const float* __restrict__ B,
    const float* __restrict__ bias, float* __restrict__ C,
    int M, int N, int K)
{
    __shared__ float As[8][128];   // transposed A tile
    __shared__ float Bs[8][128];

    const int tid = threadIdx.x;
    const int bm = blockIdx.y * 128;
    const int bn = blockIdx.x * 128;

    const int tx = tid & 15;       // 0..15  -> col group (8 cols)
    const int ty = tid >> 4;       // 0..15  -> row group (8 rows)

    const int arow = tid >> 1;          // 0..127
    const int acol = (tid & 1) * 4;     // 0 or 4
    const int brow = tid >> 5;          // 0..7
    const int bcol = (tid & 31) * 4;    // 0..124

    const float* Ap = A + (size_t)(bm + arow) * K + acol;
    const float* Bp = B + (size_t)brow * N + bn + bcol;

    float acc[8][8];
    #pragma unroll
    for (int i = 0; i < 8; ++i)
        #pragma unroll
        for (int j = 0; j < 8; ++j) acc[i][j] = 0.f;

    for (int k0 = 0; k0 < K; k0 += 8) {
        float4 a = *(const float4*)Ap;
        float4 b = *(const float4*)Bp;
        As[acol + 0][arow] = a.x;
        As[acol + 1][arow] = a.y;
        As[acol + 2][arow] = a.z;
        As[acol + 3][arow] = a.w;
        *(float4*)&Bs[brow][bcol] = b;
        __syncthreads();

        #pragma unroll
        for (int k = 0; k < 8; ++k) {
            float ar[8], br[8];
            float4 a0 = *(const float4*)&As[k][ty * 8];
            float4 a1 = *(const float4*)&As[k][ty * 8 + 4];
            float4 b0 = *(const float4*)&Bs[k][tx * 8];
            float4 b1 = *(const float4*)&Bs[k][tx * 8 + 4];
            ar[0] = a0.x; ar[1] = a0.y; ar[2] = a0.z; ar[3] = a0.w;
            ar[4] = a1.x; ar[5] = a1.y; ar[6] = a1.z; ar[7] = a1.w;
            br[0] = b0.x; br[1] = b0.y; br[2] = b0.z; br[3] = b0.w;
            br[4] = b1.x; br[5] = b1.y; br[6] = b1.z; br[7] = b1.w;
            #pragma unroll
            for (int i = 0; i < 8; ++i)
                #pragma unroll
                for (int j = 0; j < 8; ++j)
                    acc[i][j] += ar[i] * br[j];
        }
        __syncthreads();

        Ap += 8;
        Bp += (size_t)8 * N;
    }

    #pragma unroll
    for (int i = 0; i < 8; ++i) {
        const int row = bm + ty * 8 + i;
        float* Crow = C + (size_t)row * N + bn + tx * 8;
        #pragma unroll
        for (int j = 0; j < 8; j += 4) {
            const int col = bn + tx * 8 + j;
            float4 v;
            v.x = acc[i][j + 0] + bias[col + 0];
            v.y = acc[i][j + 1] + bias[col + 1];
            v.z = acc[i][j + 2] + bias[col + 2];
            v.w = acc[i][j + 3] + bias[col + 3];
            *(float4*)(Crow + j) = v;
        }
    }
}

// ---------------------------------------------------------------------------
// Flash attention (causal), fp32.
// Block = 64 threads, each thread owns one query row of a 64-row tile.
// Grid = (T/64, NHEAD).
// Q row lives in 64 registers; K,V tiles (64x64) in SMEM, read via broadcast
// float4 LDS; P staged in XOR-swizzled SMEM (conflict-free row access).
// ---------------------------------------------------------------------------
__global__ void __launch_bounds__(64) attn_kernel(
    const float* __restrict__ qkv, float* __restrict__ y)
{
    __shared__ float k_s[64][64];
    __shared__ float v_s[64][64];
    __shared__ float p_s[64][64];   // XOR-swizzled rows

    const int h = blockIdx.y;
    const int t0 = blockIdx.x * 64;
    const int tid = threadIdx.x;          // query row within tile
    const int sw = tid & 31;              // XOR swizzle key

    const int QOFF = h * DHEAD;
    const int KOFF = C_DIM + h * DHEAD;
    const int VOFF = 2 * C_DIM + h * DHEAD;
    const float scale = 0.125f;           // 1/sqrt(64)

    // Load own Q row into registers (scaled)
    float qr[DHEAD];
    {
        const float4* qp = (const float4*)(qkv + (size_t)(t0 + tid) * QKV_N + QOFF);
        #pragma unroll
        for (int d4 = 0; d4 < DHEAD / 4; ++d4) {
            float4 v = qp[d4];
            qr[d4 * 4 + 0] = v.x * scale;
            qr[d4 * 4 + 1] = v.y * scale;
            qr[d4 * 4 + 2] = v.z * scale;
            qr[d4 * 4 + 3] = v.w * scale;
        }
    }

    float o[DHEAD];
    #pragma unroll
    for (int d = 0; d < DHEAD; ++d) o[d] = 0.f;
    float m = -1e30f;
    float l = 0.f;

    const int kend = t0 + 64;   // exclusive upper bound on keys for this tile
    for (int ks = 0; ks < kend; ks += 64) {
        __syncthreads();   // protect k_s/v_s from previous iteration's readers
        // Cooperative load of K,V tiles (coalesced: thread = column)
        for (int i = 0; i < 64; ++i) {
            k_s[i][tid] = qkv[(size_t)(ks + i) * QKV_N + KOFF + tid];
            v_s[i][tid] = qkv[(size_t)(ks + i) * QKV_N + VOFF + tid];
        }
        __syncthreads();

        // --- S = q . k_j, masked, row max ---
        const int jlim = t0 + tid - ks;   // valid keys: j <= jlim
        float rowmax = -1e30f;
        for (int j = 0; j < 64; ++j) {
            const float4* krow = (const float4*)k_s[j];
            float a0 = 0.f, a1 = 0.f, a2 = 0.f, a3 = 0.f;
            #pragma unroll
            for (int k4 = 0; k4 < DHEAD / 4; ++k4) {
                float4 kv = krow[k4];   // broadcast across warp
                a0 += qr[k4 * 4 + 0] * kv.x;
                a1 += qr[k4 * 4 + 1] * kv.y;
                a2 += qr[k4 * 4 + 2] * kv.z;
                a3 += qr[k4 * 4 + 3] * kv.w;
            }
            float sv = (a0 + a1) + (a2 + a3);
            sv = (j <= jlim) ? sv : -1e30f;
            rowmax = fmaxf(rowmax, sv);
            p_s[tid][j ^ sw] = sv;
        }

        // --- online softmax rescale ---
        const float mnew = fmaxf(m, rowmax);
        const float corr = __expf(m - mnew);
        l *= corr;
        #pragma unroll
        for (int d = 0; d < DHEAD; ++d) o[d] *= corr;

        // --- P = exp(S - mnew); O += P @ V ---
        float lsum = 0.f;
        for (int j = 0; j < 64; ++j) {
            const float pj = __expf(p_s[tid][j ^ sw] - mnew);
            lsum += pj;
            const float4* vrow = (const float4*)v_s[j];
            #pragma unroll
            for (int d4 = 0; d4 < DHEAD / 4; ++d4) {
                float4 vv = vrow[d4];   // broadcast
                o[d4 * 4 + 0] += pj * vv.x;
                o[d4 * 4 + 1] += pj * vv.y;
                o[d4 * 4 + 2] += pj * vv.z;
                o[d4 * 4 + 3] += pj * vv.w;
            }
        }
        l += lsum;
        m = mnew;
    }

    // Normalize, stage through swizzled smem, write coalesced
    __syncthreads();
    const float inv = 1.f / l;
    #pragma unroll
    for (int d = 0; d < DHEAD; ++d)
        p_s[tid][d ^ sw] = o[d] * inv;
    __syncthreads();
    for (int i = 0; i < 64; ++i) {
        y[(size_t)(t0 + i) * C_DIM + h * DHEAD + tid] = p_s[i][tid ^ (i & 31)];
    }
}

// ---------------------------------------------------------------------------
extern "C" void kernel_launch(void* const* d_in, const int* in_sizes, int n_in,
                              void* d_out, int out_size)
{
    const float* x      = (const float*)d_in[0];
    const float* w_attn = (const float*)d_in[1];
    const float* b_attn = (const float*)d_in[2];
    const float* w_proj = (const float*)d_in[3];
    const float* b_proj = (const float*)d_in[4];
    float* out = (float*)d_out;

    float* qkv = nullptr;
    float* yb  = nullptr;
    cudaGetSymbolAddress((void**)&qkv, g_qkv);
    cudaGetSymbolAddress((void**)&yb, g_y);

    // 1) qkv = x @ w_attn + b_attn        [4096, 2304]
    {
        dim3 grid(QKV_N / 128, T_SEQ / 128);
        sgemm_bias_kernel<<<grid, 256>>>(x, w_attn, b_attn, qkv,
                                         T_SEQ, QKV_N, C_DIM);
    }

    // 2) attention  -> yb [4096, 768]
    {
        dim3 grid(T_SEQ / 64, NHEAD);
        attn_kernel<<<grid, 64>>>(qkv, yb);
    }

    // 3) out = yb @ w_proj + b_proj       [4096, 768]
    {
        dim3 grid(C_DIM / 128, T_SEQ / 128);
        sgemm_bias_kernel<<<grid, 256>>>(yb, w_proj, b_proj, out,
                                         T_SEQ, C_DIM, C_DIM);
    }
}

// round 3
// speedup vs baseline: 3.3055x; 3.3055x over previous
#include <cuda_runtime.h>

#define T_SEQ 4096
#define C_DIM 768
#define NHEAD 12
#define DHEAD 64
#define QKV_N (3 * C_DIM)   // 2304

// Scratch (allocation-free rule: device globals)
__device__ float g_qkv[T_SEQ * QKV_N];   // [T, 3C]
__device__ float g_y[T_SEQ * C_DIM];     // [T, C]

__device__ __forceinline__ unsigned f2tf(float f) {
    unsigned u;
    asm("cvt.rna.tf32.f32 %0, %1;" : "=r"(u) : "f"(f));
    return u;
}

__device__ __forceinline__ void mma8(float* d, const unsigned* a, const unsigned* b) {
    asm volatile(
        "mma.sync.aligned.m16n8k8.row.col.f32.tf32.tf32.f32 "
        "{%0,%1,%2,%3},{%4,%5,%6,%7},{%8,%9},{%0,%1,%2,%3};\n"
        : "+f"(d[0]), "+f"(d[1]), "+f"(d[2]), "+f"(d[3])
        : "r"(a[0]), "r"(a[1]), "r"(a[2]), "r"(a[3]), "r"(b[0]), "r"(b[1]));
}

// ---------------------------------------------------------------------------
// TF32 tensor-core GEMM: C[M,N] = A[M,K] @ B[K,N] + bias[N]
// BM=BN=128, BK=16, 256 threads (8 warps), warp tile 32x64 (2x8 m16n8k8).
// Requires M%128==0, N%128==0, K%16==0.
// ---------------------------------------------------------------------------
__global__ void __launch_bounds__(256) gemm_tf32(
    const float* __restrict__ A, const float* __restrict__ B,
    const float* __restrict__ bias, float* __restrict__ C,
    int M, int N, int K)
{
    __shared__ float As[2][16][136];   // As[k][m], pad 8 -> conflict-free frag loads
    __shared__ float Bs[2][16][136];   // Bs[k][n]

    const int tid = threadIdx.x, lane = tid & 31, warp = tid >> 5;
    const int r = lane >> 2, c = lane & 3;
    const int wm = (warp & 3) * 32, wn = (warp >> 2) * 64;
    const int bm = blockIdx.y * 128, bn = blockIdx.x * 128;

    const float* Ag = A + (size_t)(bm + (tid >> 1)) * K + (tid & 1) * 8;
    const float* Bg = B + (size_t)(tid >> 5) * N + bn + (tid & 31) * 4;

    float4 pa0 = *(const float4*)Ag;
    float4 pa1 = *(const float4*)(Ag + 4);
    float4 pb0 = *(const float4*)Bg;
    float4 pb1 = *(const float4*)(Bg + (size_t)8 * N);

    float acc[2][8][4];
    #pragma unroll
    for (int i = 0; i < 2; ++i)
        #pragma unroll
        for (int j = 0; j < 8; ++j)
            #pragma unroll
            for (int q = 0; q < 4; ++q) acc[i][j][q] = 0.f;

    int buf = 0;
    for (int k0 = 0; k0 < K; k0 += 16) {
        const int arow = tid >> 1, acol = (tid & 1) * 8;
        As[buf][acol + 0][arow] = pa0.x;
        As[buf][acol + 1][arow] = pa0.y;
        As[buf][acol + 2][arow] = pa0.z;
        As[buf][acol + 3][arow] = pa0.w;
        As[buf][acol + 4][arow] = pa1.x;
        As[buf][acol + 5][arow] = pa1.y;
        As[buf][acol + 6][arow] = pa1.z;
        As[buf][acol + 7][arow] = pa1.w;
        const int brow = tid >> 5, bcol = (tid & 31) * 4;
        *(float4*)&Bs[buf][brow][bcol] = pb0;
        *(float4*)&Bs[buf][brow + 8][bcol] = pb1;
        __syncthreads();

        if (k0 + 16 < K) {
            Ag += 16;
            Bg += (size_t)16 * N;
            pa0 = *(const float4*)Ag;
            pa1 = *(const float4*)(Ag + 4);
            pb0 = *(const float4*)Bg;
            pb1 = *(const float4*)(Bg + (size_t)8 * N);
        }

        #pragma unroll
        for (int kk = 0; kk < 16; kk += 8) {
            unsigned af[2][4], bf[8][2];
            #pragma unroll
            for (int mi = 0; mi < 2; ++mi) {
                af[mi][0] = f2tf(As[buf][kk + c    ][wm + mi * 16 + r    ]);
                af[mi][1] = f2tf(As[buf][kk + c    ][wm + mi * 16 + r + 8]);
                af[mi][2] = f2tf(As[buf][kk + c + 4][wm + mi * 16 + r    ]);
                af[mi][3] = f2tf(As[buf][kk + c + 4][wm + mi * 16 + r + 8]);
            }
            #pragma unroll
            for (int ni = 0; ni < 8; ++ni) {
                bf[ni][0] = f2tf(Bs[buf][kk + c    ][wn + ni * 8 + r]);
                bf[ni][1] = f2tf(Bs[buf][kk + c + 4][wn + ni * 8 + r]);
            }
            #pragma unroll
            for (int mi = 0; mi < 2; ++mi)
                #pragma unroll
                for (int ni = 0; ni < 8; ++ni)
                    mma8(acc[mi][ni], af[mi], bf[ni]);
        }
        buf ^= 1;
    }

    #pragma unroll
    for (int mi = 0; mi < 2; ++mi)
        #pragma unroll
        for (int ni = 0; ni < 8; ++ni) {
            const int grow = bm + wm + mi * 16 + r;
            const int gcol = bn + wn + ni * 8 + 2 * c;
            const float b0 = bias[gcol], b1 = bias[gcol + 1];
            float2 v0 = make_float2(acc[mi][ni][0] + b0, acc[mi][ni][1] + b1);
            float2 v1 = make_float2(acc[mi][ni][2] + b0, acc[mi][ni][3] + b1);
            *(float2*)&C[(size_t)grow * N + gcol] = v0;
            *(float2*)&C[(size_t)(grow + 8) * N + gcol] = v1;
        }
}

// ---------------------------------------------------------------------------
// Flash attention (causal) with tf32 tensor cores.
// Block: 256 threads (8 warps), 128 query rows, one head. Key tiles of 64.
// Warp w owns query rows [16w, 16w+16). S and O live in mma accumulators.
// ---------------------------------------------------------------------------
__global__ void __launch_bounds__(256) attn_tf32(
    const float* __restrict__ qkv, float* __restrict__ y)
{
    extern __shared__ float sm[];
    float* Ks = sm;                  // [64][72]
    float* Vs = sm + 64 * 72;        // [64][72]
    float* Ps = sm + 2 * 64 * 72;    // [128][72]  (also Q staging)

    const int h = blockIdx.y;
    const int t0 = (gridDim.x - 1 - blockIdx.x) * 128;   // longest blocks first
    const int tid = threadIdx.x, lane = tid & 31, warp = tid >> 5;
    const int r = lane >> 2, c = lane & 3;
    const int q0 = warp * 16;

    // --- stage Q tile [128][64] into Ps ---
    {
        const int i = tid >> 1;
        const int dbase = (tid & 1) * 32;
        const float* src = qkv + (size_t)(t0 + i) * QKV_N + h * DHEAD + dbase;
        float* dst = Ps + i * 72 + dbase;
        #pragma unroll
        for (int l = 0; l < 8; ++l)
            ((float4*)dst)[l] = ((const float4*)src)[l];
    }
    __syncthreads();

    // Q fragments (scaled by 1/sqrt(D))
    unsigned qf[8][4];
    #pragma unroll
    for (int kk = 0; kk < 8; ++kk) {
        qf[kk][0] = f2tf(Ps[(q0 + r    ) * 72 + kk * 8 + c    ] * 0.125f);
        qf[kk][1] = f2tf(Ps[(q0 + r + 8) * 72 + kk * 8 + c    ] * 0.125f);
        qf[kk][2] = f2tf(Ps[(q0 + r    ) * 72 + kk * 8 + c + 4] * 0.125f);
        qf[kk][3] = f2tf(Ps[(q0 + r + 8) * 72 + kk * 8 + c + 4] * 0.125f);
    }
    __syncthreads();   // Q consumed; Ps free for P

    float oacc[8][4];
    #pragma unroll
    for (int ni = 0; ni < 8; ++ni)
        #pragma unroll
        for (int q = 0; q < 4; ++q) oacc[ni][q] = 0.f;

    float m0 = -1e30f, m1 = -1e30f, l0 = 0.f, l1 = 0.f;
    const int row0 = t0 + q0 + r;
    const int row1 = row0 + 8;

    for (int ks = 0; ks < t0 + 128; ks += 64) {
        // --- load K,V tiles ---
        {
            const int key = tid >> 2;
            const size_t base = (size_t)(ks + key) * QKV_N + h * DHEAD;
            #pragma unroll
            for (int l = 0; l < 4; ++l) {
                const int d = ((tid & 3) + l * 4) * 4;
                *(float4*)&Ks[key * 72 + d] = *(const float4*)&qkv[base + C_DIM + d];
                *(float4*)&Vs[key * 72 + d] = *(const float4*)&qkv[base + 2 * C_DIM + d];
            }
        }
        __syncthreads();

        // --- S = Q @ K^T ---
        float sacc[8][4];
        #pragma unroll
        for (int ni = 0; ni < 8; ++ni)
            #pragma unroll
            for (int q = 0; q < 4; ++q) sacc[ni][q] = 0.f;

        #pragma unroll
        for (int kk = 0; kk < 8; ++kk) {
            unsigned bf[8][2];
            #pragma unroll
            for (int ni = 0; ni < 8; ++ni) {
                bf[ni][0] = f2tf(Ks[(ni * 8 + r) * 72 + kk * 8 + c    ]);
                bf[ni][1] = f2tf(Ks[(ni * 8 + r) * 72 + kk * 8 + c + 4]);
            }
            #pragma unroll
            for (int ni = 0; ni < 8; ++ni)
                mma8(sacc[ni], qf[kk], bf[ni]);
        }

        // --- causal mask (only near/above diagonal) ---
        if (ks + 63 > t0 + q0) {
            #pragma unroll
            for (int ni = 0; ni < 8; ++ni) {
                const int col = ks + ni * 8 + 2 * c;
                if (col     > row0) sacc[ni][0] = -1e30f;
                if (col + 1 > row0) sacc[ni][1] = -1e30f;
                if (col     > row1) sacc[ni][2] = -1e30f;
                if (col + 1 > row1) sacc[ni][3] = -1e30f;
            }
        }

        // --- online softmax ---
        float rm0 = -1e30f, rm1 = -1e30f;
        #pragma unroll
        for (int ni = 0; ni < 8; ++ni) {
            rm0 = fmaxf(rm0, fmaxf(sacc[ni][0], sacc[ni][1]));
            rm1 = fmaxf(rm1, fmaxf(sacc[ni][2], sacc[ni][3]));
        }
        rm0 = fmaxf(rm0, __shfl_xor_sync(0xffffffffu, rm0, 1));
        rm0 = fmaxf(rm0, __shfl_xor_sync(0xffffffffu, rm0, 2));
        rm1 = fmaxf(rm1, __shfl_xor_sync(0xffffffffu, rm1, 1));
        rm1 = fmaxf(rm1, __shfl_xor_sync(0xffffffffu, rm1, 2));

        const float mn0 = fmaxf(m0, rm0), mn1 = fmaxf(m1, rm1);
        const float co0 = __expf(m0 - mn0), co1 = __expf(m1 - mn1);

        float ls0 = 0.f, ls1 = 0.f;
        #pragma unroll
        for (int ni = 0; ni < 8; ++ni) {
            const float p00 = __expf(sacc[ni][0] - mn0);
            const float p01 = __expf(sacc[ni][1] - mn0);
            const float p10 = __expf(sacc[ni][2] - mn1);
            const float p11 = __expf(sacc[ni][3] - mn1);
            ls0 += p00 + p01;
            ls1 += p10 + p11;
            Ps[(q0 + r    ) * 72 + ni * 8 + 2 * c    ] = p00;
            Ps[(q0 + r    ) * 72 + ni * 8 + 2 * c + 1] = p01;
            Ps[(q0 + r + 8) * 72 + ni * 8 + 2 * c    ] = p10;
            Ps[(q0 + r + 8) * 72 + ni * 8 + 2 * c + 1] = p11;
            oacc[ni][0] *= co0; oacc[ni][1] *= co0;
            oacc[ni][2] *= co1; oacc[ni][3] *= co1;
        }
        ls0 += __shfl_xor_sync(0xffffffffu, ls0, 1);
        ls0 += __shfl_xor_sync(0xffffffffu, ls0, 2);
        ls1 += __shfl_xor_sync(0xffffffffu, ls1, 1);
        ls1 += __shfl_xor_sync(0xffffffffu, ls1, 2);
        l0 = l0 * co0 + ls0;
        l1 = l1 * co1 + ls1;
        m0 = mn0; m1 = mn1;
        __syncwarp();   // P rows are warp-local: warp-level visibility suffices

        // --- O += P @ V ---
        #pragma unroll
        for (int kk = 0; kk < 8; ++kk) {
            unsigned pf[4];
            pf[0] = f2tf(Ps[(q0 + r    ) * 72 + kk * 8 + c    ]);
            pf[1] = f2tf(Ps[(q0 + r + 8) * 72 + kk * 8 + c    ]);
            pf[2] = f2tf(Ps[(q0 + r    ) * 72 + kk * 8 + c + 4]);
            pf[3] = f2tf(Ps[(q0 + r + 8) * 72 + kk * 8 + c + 4]);
            #pragma unroll
            for (int ni = 0; ni < 8; ++ni) {
                unsigned vv[2];
                vv[0] = f2tf(Vs[(kk * 8 + c    ) * 72 + ni * 8 + r]);
                vv[1] = f2tf(Vs[(kk * 8 + c + 4) * 72 + ni * 8 + r]);
                mma8(oacc[ni], pf, vv);
            }
        }
        __syncthreads();   // protect Ks/Vs before next tile load
    }

    // --- normalize & store ---
    const float inv0 = 1.f / l0, inv1 = 1.f / l1;
    #pragma unroll
    for (int ni = 0; ni < 8; ++ni) {
        const int gc = h * DHEAD + ni * 8 + 2 * c;
        float2 v0 = make_float2(oacc[ni][0] * inv0, oacc[ni][1] * inv0);
        float2 v1 = make_float2(oacc[ni][2] * inv1, oacc[ni][3] * inv1);
        *(float2*)&y[(size_t)(t0 + q0 + r    ) * C_DIM + gc] = v0;
        *(float2*)&y[(size_t)(t0 + q0 + r + 8) * C_DIM + gc] = v1;
    }
}

// ---------------------------------------------------------------------------
extern "C" void kernel_launch(void* const* d_in, const int* in_sizes, int n_in,
                              void* d_out, int out_size)
{
    const float* x      = (const float*)d_in[0];
    const float* w_attn = (const float*)d_in[1];
    const float* b_attn = (const float*)d_in[2];
    const float* w_proj = (const float*)d_in[3];
    const float* b_proj = (const float*)d_in[4];
    float* out = (float*)d_out;

    float* qkv = nullptr;
    float* yb  = nullptr;
    cudaGetSymbolAddress((void**)&qkv, g_qkv);
    cudaGetSymbolAddress((void**)&yb, g_y);

    const int attn_smem = (2 * 64 * 72 + 128 * 72) * 4;   // 73728 B
    static bool attr_set = false;
    if (!attr_set) {
        cudaFuncSetAttribute(attn_tf32,
                             cudaFuncAttributeMaxDynamicSharedMemorySize,
                             attn_smem);
        attr_set = true;
    }

    // 1) qkv = x @ w_attn + b_attn        [4096, 2304]
    {
        dim3 grid(QKV_N / 128, T_SEQ / 128);
        gemm_tf32<<<grid, 256>>>(x, w_attn, b_attn, qkv, T_SEQ, QKV_N, C_DIM);
    }

    // 2) attention  -> yb [4096, 768]
    {
        dim3 grid(T_SEQ / 128, NHEAD);
        attn_tf32<<<grid, 256, attn_smem>>>(qkv, yb);
    }

    // 3) out = yb @ w_proj + b_proj       [4096, 768]
    {
        dim3 grid(C_DIM / 128, T_SEQ / 128);
        gemm_tf32<<<grid, 256>>>(yb, w_proj, b_proj, out, T_SEQ, C_DIM, C_DIM);
    }
}

// round 4
// speedup vs baseline: 3.3707x; 1.0197x over previous
#include <cuda_runtime.h>

#define T_SEQ 4096
#define C_DIM 768
#define NHEAD 12
#define DHEAD 64
#define QKV_N (3 * C_DIM)   // 2304

// Scratch (allocation-free rule: device globals)
__device__ float g_qkv[T_SEQ * QKV_N];   // [T, 3C]
__device__ float g_y[T_SEQ * C_DIM];     // [T, C]

__device__ __forceinline__ unsigned f2tf(float f) {
    unsigned u;
    asm("cvt.rna.tf32.f32 %0, %1;" : "=r"(u) : "f"(f));
    return u;
}

__device__ __forceinline__ void mma8(float* d, const unsigned* a, const unsigned* b) {
    asm volatile(
        "mma.sync.aligned.m16n8k8.row.col.f32.tf32.tf32.f32 "
        "{%0,%1,%2,%3},{%4,%5,%6,%7},{%8,%9},{%0,%1,%2,%3};\n"
        : "+f"(d[0]), "+f"(d[1]), "+f"(d[2]), "+f"(d[3])
        : "r"(a[0]), "r"(a[1]), "r"(a[2]), "r"(a[3]), "r"(b[0]), "r"(b[1]));
}

// ---------------------------------------------------------------------------
// TF32 tensor-core GEMM: C[M,N] = A[M,K] @ B[K,N] + bias[N]
// BM=BN=128, BK=16, 256 threads (8 warps), warp tile 32x64 (2x8 m16n8k8).
// Requires M%128==0, N%128==0, K%16==0.
// ---------------------------------------------------------------------------
__global__ void __launch_bounds__(256) gemm_tf32(
    const float* __restrict__ A, const float* __restrict__ B,
    const float* __restrict__ bias, float* __restrict__ C,
    int M, int N, int K)
{
    __shared__ float As[2][16][136];   // As[k][m], pad 8 -> conflict-free frag loads
    __shared__ float Bs[2][16][136];   // Bs[k][n]

    const int tid = threadIdx.x, lane = tid & 31, warp = tid >> 5;
    const int r = lane >> 2, c = lane & 3;
    const int wm = (warp & 3) * 32, wn = (warp >> 2) * 64;
    const int bm = blockIdx.y * 128, bn = blockIdx.x * 128;

    const float* Ag = A + (size_t)(bm + (tid >> 1)) * K + (tid & 1) * 8;
    const float* Bg = B + (size_t)(tid >> 5) * N + bn + (tid & 31) * 4;

    float4 pa0 = *(const float4*)Ag;
    float4 pa1 = *(const float4*)(Ag + 4);
    float4 pb0 = *(const float4*)Bg;
    float4 pb1 = *(const float4*)(Bg + (size_t)8 * N);

    float acc[2][8][4];
    #pragma unroll
    for (int i = 0; i < 2; ++i)
        #pragma unroll
        for (int j = 0; j < 8; ++j)
            #pragma unroll
            for (int q = 0; q < 4; ++q) acc[i][j][q] = 0.f;

    int buf = 0;
    for (int k0 = 0; k0 < K; k0 += 16) {
        const int arow = tid >> 1, acol = (tid & 1) * 8;
        As[buf][acol + 0][arow] = pa0.x;
        As[buf][acol + 1][arow] = pa0.y;
        As[buf][acol + 2][arow] = pa0.z;
        As[buf][acol + 3][arow] = pa0.w;
        As[buf][acol + 4][arow] = pa1.x;
        As[buf][acol + 5][arow] = pa1.y;
        As[buf][acol + 6][arow] = pa1.z;
        As[buf][acol + 7][arow] = pa1.w;
        const int brow = tid >> 5, bcol = (tid & 31) * 4;
        *(float4*)&Bs[buf][brow][bcol] = pb0;
        *(float4*)&Bs[buf][brow + 8][bcol] = pb1;
        __syncthreads();

        if (k0 + 16 < K) {
            Ag += 16;
            Bg += (size_t)16 * N;
            pa0 = *(const float4*)Ag;
            pa1 = *(const float4*)(Ag + 4);
            pb0 = *(const float4*)Bg;
            pb1 = *(const float4*)(Bg + (size_t)8 * N);
        }

        #pragma unroll
        for (int kk = 0; kk < 16; kk += 8) {
            unsigned af[2][4], bf[8][2];
            #pragma unroll
            for (int mi = 0; mi < 2; ++mi) {
                af[mi][0] = f2tf(As[buf][kk + c    ][wm + mi * 16 + r    ]);
                af[mi][1] = f2tf(As[buf][kk + c    ][wm + mi * 16 + r + 8]);
                af[mi][2] = f2tf(As[buf][kk + c + 4][wm + mi * 16 + r    ]);
                af[mi][3] = f2tf(As[buf][kk + c + 4][wm + mi * 16 + r + 8]);
            }
            #pragma unroll
            for (int ni = 0; ni < 8; ++ni) {
                bf[ni][0] = f2tf(Bs[buf][kk + c    ][wn + ni * 8 + r]);
                bf[ni][1] = f2tf(Bs[buf][kk + c + 4][wn + ni * 8 + r]);
            }
            #pragma unroll
            for (int mi = 0; mi < 2; ++mi)
                #pragma unroll
                for (int ni = 0; ni < 8; ++ni)
                    mma8(acc[mi][ni], af[mi], bf[ni]);
        }
        buf ^= 1;
    }

    #pragma unroll
    for (int mi = 0; mi < 2; ++mi)
        #pragma unroll
        for (int ni = 0; ni < 8; ++ni) {
            const int grow = bm + wm + mi * 16 + r;
            const int gcol = bn + wn + ni * 8 + 2 * c;
            const float b0 = bias[gcol], b1 = bias[gcol + 1];
            float2 v0 = make_float2(acc[mi][ni][0] + b0, acc[mi][ni][1] + b1);
            float2 v1 = make_float2(acc[mi][ni][2] + b0, acc[mi][ni][3] + b1);
            *(float2*)&C[(size_t)grow * N + gcol] = v0;
            *(float2*)&C[(size_t)(grow + 8) * N + gcol] = v1;
        }
}

// ---------------------------------------------------------------------------
// Flash attention (causal) with tf32 tensor cores.
// Block: 256 threads (8 warps), 128 query rows, one head. Key tiles of 64.
// Warp w owns query rows [16w, 16w+16). S and O live in mma accumulators.
// ---------------------------------------------------------------------------
__global__ void __launch_bounds__(256) attn_tf32(
    const float* __restrict__ qkv, float* __restrict__ y)
{
    extern __shared__ float sm[];
    float* Ks = sm;                  // [64][72]
    float* Vs = sm + 64 * 72;        // [64][72]
    float* Ps = sm + 2 * 64 * 72;    // [128][72]  (also Q staging)

    const int h = blockIdx.y;
    const int t0 = (gridDim.x - 1 - blockIdx.x) * 128;   // longest blocks first
    const int tid = threadIdx.x, lane = tid & 31, warp = tid >> 5;
    const int r = lane >> 2, c = lane & 3;
    const int q0 = warp * 16;

    // --- stage Q tile [128][64] into Ps ---
    {
        const int i = tid >> 1;
        const int dbase = (tid & 1) * 32;
        const float* src = qkv + (size_t)(t0 + i) * QKV_N + h * DHEAD + dbase;
        float* dst = Ps + i * 72 + dbase;
        #pragma unroll
        for (int l = 0; l < 8; ++l)
            ((float4*)dst)[l] = ((const float4*)src)[l];
    }
    __syncthreads();

    // Q fragments (scaled by 1/sqrt(D))
    unsigned qf[8][4];
    #pragma unroll
    for (int kk = 0; kk < 8; ++kk) {
        qf[kk][0] = f2tf(Ps[(q0 + r    ) * 72 + kk * 8 + c    ] * 0.125f);
        qf[kk][1] = f2tf(Ps[(q0 + r + 8) * 72 + kk * 8 + c    ] * 0.125f);
        qf[kk][2] = f2tf(Ps[(q0 + r    ) * 72 + kk * 8 + c + 4] * 0.125f);
        qf[kk][3] = f2tf(Ps[(q0 + r + 8) * 72 + kk * 8 + c + 4] * 0.125f);
    }
    __syncthreads();   // Q consumed; Ps free for P

    float oacc[8][4];
    #pragma unroll
    for (int ni = 0; ni < 8; ++ni)
        #pragma unroll
        for (int q = 0; q < 4; ++q) oacc[ni][q] = 0.f;

    float m0 = -1e30f, m1 = -1e30f, l0 = 0.f, l1 = 0.f;
    const int row0 = t0 + q0 + r;
    const int row1 = row0 + 8;

    for (int ks = 0; ks < t0 + 128; ks += 64) {
        // --- load K,V tiles ---
        {
            const int key = tid >> 2;
            const size_t base = (size_t)(ks + key) * QKV_N + h * DHEAD;
            #pragma unroll
            for (int l = 0; l < 4; ++l) {
                const int d = ((tid & 3) + l * 4) * 4;
                *(float4*)&Ks[key * 72 + d] = *(const float4*)&qkv[base + C_DIM + d];
                *(float4*)&Vs[key * 72 + d] = *(const float4*)&qkv[base + 2 * C_DIM + d];
            }
        }
        __syncthreads();

        // --- S = Q @ K^T ---
        float sacc[8][4];
        #pragma unroll
        for (int ni = 0; ni < 8; ++ni)
            #pragma unroll
            for (int q = 0; q < 4; ++q) sacc[ni][q] = 0.f;

        #pragma unroll
        for (int kk = 0; kk < 8; ++kk) {
            unsigned bf[8][2];
            #pragma unroll
            for (int ni = 0; ni < 8; ++ni) {
                bf[ni][0] = f2tf(Ks[(ni * 8 + r) * 72 + kk * 8 + c    ]);
                bf[ni][1] = f2tf(Ks[(ni * 8 + r) * 72 + kk * 8 + c + 4]);
            }
            #pragma unroll
            for (int ni = 0; ni < 8; ++ni)
                mma8(sacc[ni], qf[kk], bf[ni]);
        }

        // --- causal mask (only near/above diagonal) ---
        if (ks + 63 > t0 + q0) {
            #pragma unroll
            for (int ni = 0; ni < 8; ++ni) {
                const int col = ks + ni * 8 + 2 * c;
                if (col     > row0) sacc[ni][0] = -1e30f;
                if (col + 1 > row0) sacc[ni][1] = -1e30f;
                if (col     > row1) sacc[ni][2] = -1e30f;
                if (col + 1 > row1) sacc[ni][3] = -1e30f;
            }
        }

        // --- online softmax ---
        float rm0 = -1e30f, rm1 = -1e30f;
        #pragma unroll
        for (int ni = 0; ni < 8; ++ni) {
            rm0 = fmaxf(rm0, fmaxf(sacc[ni][0], sacc[ni][1]));
            rm1 = fmaxf(rm1, fmaxf(sacc[ni][2], sacc[ni][3]));
        }
        rm0 = fmaxf(rm0, __shfl_xor_sync(0xffffffffu, rm0, 1));
        rm0 = fmaxf(rm0, __shfl_xor_sync(0xffffffffu, rm0, 2));
        rm1 = fmaxf(rm1, __shfl_xor_sync(0xffffffffu, rm1, 1));
        rm1 = fmaxf(rm1, __shfl_xor_sync(0xffffffffu, rm1, 2));

        const float mn0 = fmaxf(m0, rm0), mn1 = fmaxf(m1, rm1);
        const float co0 = __expf(m0 - mn0), co1 = __expf(m1 - mn1);

        float ls0 = 0.f, ls1 = 0.f;
        #pragma unroll
        for (int ni = 0; ni < 8; ++ni) {
            const float p00 = __expf(sacc[ni][0] - mn0);
            const float p01 = __expf(sacc[ni][1] - mn0);
            const float p10 = __expf(sacc[ni][2] - mn1);
            const float p11 = __expf(sacc[ni][3] - mn1);
            ls0 += p00 + p01;
            ls1 += p10 + p11;
            Ps[(q0 + r    ) * 72 + ni * 8 + 2 * c    ] = p00;
            Ps[(q0 + r    ) * 72 + ni * 8 + 2 * c + 1] = p01;
            Ps[(q0 + r + 8) * 72 + ni * 8 + 2 * c    ] = p10;
            Ps[(q0 + r + 8) * 72 + ni * 8 + 2 * c + 1] = p11;
            oacc[ni][0] *= co0; oacc[ni][1] *= co0;
            oacc[ni][2] *= co1; oacc[ni][3] *= co1;
        }
        ls0 += __shfl_xor_sync(0xffffffffu, ls0, 1);
        ls0 += __shfl_xor_sync(0xffffffffu, ls0, 2);
        ls1 += __shfl_xor_sync(0xffffffffu, ls1, 1);
        ls1 += __shfl_xor_sync(0xffffffffu, ls1, 2);
        l0 = l0 * co0 + ls0;
        l1 = l1 * co1 + ls1;
        m0 = mn0; m1 = mn1;
        __syncwarp();   // P rows are warp-local: warp-level visibility suffices

        // --- O += P @ V ---
        #pragma unroll
        for (int kk = 0; kk < 8; ++kk) {
            unsigned pf[4];
            pf[0] = f2tf(Ps[(q0 + r    ) * 72 + kk * 8 + c    ]);
            pf[1] = f2tf(Ps[(q0 + r + 8) * 72 + kk * 8 + c    ]);
            pf[2] = f2tf(Ps[(q0 + r    ) * 72 + kk * 8 + c + 4]);
            pf[3] = f2tf(Ps[(q0 + r + 8) * 72 + kk * 8 + c + 4]);
            #pragma unroll
            for (int ni = 0; ni < 8; ++ni) {
                unsigned vv[2];
                vv[0] = f2tf(Vs[(kk * 8 + c    ) * 72 + ni * 8 + r]);
                vv[1] = f2tf(Vs[(kk * 8 + c + 4) * 72 + ni * 8 + r]);
                mma8(oacc[ni], pf, vv);
            }
        }
        __syncthreads();   // protect Ks/Vs before next tile load
    }

    // --- normalize & store ---
    const float inv0 = 1.f / l0, inv1 = 1.f / l1;
    #pragma unroll
    for (int ni = 0; ni < 8; ++ni) {
        const int gc = h * DHEAD + ni * 8 + 2 * c;
        float2 v0 = make_float2(oacc[ni][0] * inv0, oacc[ni][1] * inv0);
        float2 v1 = make_float2(oacc[ni][2] * inv1, oacc[ni][3] * inv1);
        *(float2*)&y[(size_t)(t0 + q0 + r    ) * C_DIM + gc] = v0;
        *(float2*)&y[(size_t)(t0 + q0 + r + 8) * C_DIM + gc] = v1;
    }
}

// ---------------------------------------------------------------------------
extern "C" void kernel_launch(void* const* d_in, const int* in_sizes, int n_in,
                              void* d_out, int out_size)
{
    const float* x      = (const float*)d_in[0];
    const float* w_attn = (const float*)d_in[1];
    const float* b_attn = (const float*)d_in[2];
    const float* w_proj = (const float*)d_in[3];
    const float* b_proj = (const float*)d_in[4];
    float* out = (float*)d_out;

    float* qkv = nullptr;
    float* yb  = nullptr;
    cudaGetSymbolAddress((void**)&qkv, g_qkv);
    cudaGetSymbolAddress((void**)&yb, g_y);

    const int attn_smem = (2 * 64 * 72 + 128 * 72) * 4;   // 73728 B
    static bool attr_set = false;
    if (!attr_set) {
        cudaFuncSetAttribute(attn_tf32,
                             cudaFuncAttributeMaxDynamicSharedMemorySize,
                             attn_smem);
        attr_set = true;
    }

    // 1) qkv = x @ w_attn + b_attn        [4096, 2304]
    {
        dim3 grid(QKV_N / 128, T_SEQ / 128);
        gemm_tf32<<<grid, 256>>>(x, w_attn, b_attn, qkv, T_SEQ, QKV_N, C_DIM);
    }

    // 2) attention  -> yb [4096, 768]
    {
        dim3 grid(T_SEQ / 128, NHEAD);
        attn_tf32<<<grid, 256, attn_smem>>>(qkv, yb);
    }

    // 3) out = yb @ w_proj + b_proj       [4096, 768]
    {
        dim3 grid(C_DIM / 128, T_SEQ / 128);
        gemm_tf32<<<grid, 256>>>(yb, w_proj, b_proj, out, T_SEQ, C_DIM, C_DIM);
    }
}